// round 17
// baseline (speedup 1.0000x reference)
#include <cuda_runtime.h>
#include <stdint.h>

#define NPTS   8192
#define RAD2   64.0f           // radius^2 (radius = 8.0)
#define SPLIT  32              // j-split for rank counting (window = 256)
#define GRIDW  32              // 32x32 cells of 16px (512/16)
#define NCELLS (GRIDW * GRIDW)
#define CAP    40              // max points per cell slab
#define MAXDEG 32              // backward (higher-rank) neighbors per point
#define SOLVT  1024            // solver threads (warp 0 resolves)

typedef unsigned long long ull;

// ---- device scratch (no allocations allowed; zero-init, re-zeroed by solve) ----
__device__ int      g_partial[SPLIT][NPTS];
__device__ int      g_rank[NPTS];                           // orig idx -> rank
__device__ int      g_order[NPTS];                          // rank -> orig idx
__device__ float    g_ss[NPTS];                             // rank -> score
__device__ int      g_acnt[NPTS];                           // rank -> backward degree (atomic)
__device__ __align__(16) uint16_t g_radj[NPTS * MAXDEG];    // rank -> neighbor RANKS (set)
__device__ int      g_ccnt[NCELLS];                         // points per cell (atomic)
__device__ __align__(16) float4 g_cell_rec[NCELLS * CAP];   // cell slabs {x, y, rank_bits, 0}

// 64-bit key: ascending <=> (score desc, index asc)  [stable argsort(-s)]
__device__ __forceinline__ ull sort_key(float f, int idx) {
    uint32_t b = __float_as_uint(f);
    b ^= (b & 0x80000000u) ? 0xFFFFFFFFu : 0x80000000u;
    return ((ull)(~b) << 13) | (uint32_t)idx;
}

// ========== K1: partial ranks. grid (32, SPLIT) x 256, window = 256 ==========
__global__ void rank_partial_kernel(const float* __restrict__ scores) {
    const int tid = threadIdx.x;
    const int i   = blockIdx.x * 256 + tid;
    const int by  = blockIdx.y;

    const ull ki = sort_key(scores[i], i);
    __shared__ ull s_k[256];
    const int j0 = by * 256;
    s_k[tid] = sort_key(scores[j0 + tid], j0 + tid);
    __syncthreads();

    int cnt = 0;
    #pragma unroll 16
    for (int jj = 0; jj < 256; ++jj)
        cnt += (s_k[jj] < ki);
    g_partial[by][i] = cnt;
}

// ========== K2: combine ranks + scatter + cell fill (g_ccnt zero on entry).
// grid 32 x 256 ==========
__global__ void combine_fill_kernel(const float* __restrict__ scores,
                                    const float* __restrict__ coords) {
    const int i = blockIdx.x * 256 + threadIdx.x;
    int rank = 0;
    #pragma unroll
    for (int s = 0; s < SPLIT; ++s) rank += g_partial[s][i];
    const float x = coords[2 * i], y = coords[2 * i + 1];
    g_rank[i]     = rank;
    g_order[rank] = i;
    g_ss[rank]    = scores[i];

    const int cx = min(GRIDW - 1, (int)(x * 0.0625f));
    const int cy = min(GRIDW - 1, (int)(y * 0.0625f));
    const int cell = cy * GRIDW + cx;
    const int slot = atomicAdd(&g_ccnt[cell], 1);
    if (slot < CAP)
        g_cell_rec[cell * CAP + slot] = make_float4(x, y, __int_as_float(rank), 0.0f);
}

// ========== K3: backward adjacency, 3 threads per point (one per cell-row).
// 4-wide clamped-load unroll (MLP=4). Neighbor SET deterministic. grid 192x128 ==========
__global__ void adj_kernel(const float* __restrict__ coords) {
    const int g   = blockIdx.x * 128 + threadIdx.x;    // 24576 threads
    const int i   = g & (NPTS - 1);
    const int row = g >> 13;                           // 0..2

    const float xi = coords[2 * i], yi = coords[2 * i + 1];
    const int cx = min(GRIDW - 1, (int)(xi * 0.0625f));
    const int cy = min(GRIDW - 1, (int)(yi * 0.0625f));
    const int yy = cy + row - 1;
    if (yy < 0 || yy >= GRIDW) return;
    const int ri = g_rank[i];
    const int x0 = max(cx - 1, 0), x1 = min(cx + 1, GRIDW - 1);

    for (int xx = x0; xx <= x1; ++xx) {
        const int cell = yy * GRIDW + xx;
        const int cnt  = min(g_ccnt[cell], CAP);
        if (cnt <= 0) continue;
        const int base = cell * CAP;
        const int last = base + cnt - 1;

        for (int k = base; k < base + cnt; k += 4) {
            const float4 r0 = g_cell_rec[k];
            const float4 r1 = g_cell_rec[min(k + 1, last)];
            const float4 r2 = g_cell_rec[min(k + 2, last)];
            const float4 r3 = g_cell_rec[min(k + 3, last)];

            #pragma unroll
            for (int j = 0; j < 4; ++j) {
                const float4 rec = (j == 0) ? r0 : (j == 1) ? r1 : (j == 2) ? r2 : r3;
                if (k + j <= last) {
                    const int rj = __float_as_int(rec.z);
                    if (rj < ri) {
                        const float dx = xi - rec.x;
                        const float dy = yi - rec.y;
                        const float d2 = dx * dx + dy * dy;   // identical fp expr
                        if (d2 < RAD2) {
                            const int slot = atomicAdd(&g_acnt[ri], 1);
                            if (slot < MAXDEG)
                                g_radj[ri * MAXDEG + slot] = (uint16_t)rj;
                        }
                    }
                }
            }
        }
    }
}

// ========== K4: warp-sequential Gauss-Seidel over 32-rank chunks.
// 1024 threads preload adjacency (first 8 nbrs) + degrees to smem; warp 0
// then resolves 256 chunks IN ORDER with zero block barriers:
//   lower-chunk nbrs -> published smem keep-bit probes (final values),
//   intra-chunk nbrs -> lane bitmask + ballot Jacobi (<= depth iters;
//   ballot-stability certificate => unique well-founded fixpoint == greedy).
// ==========
__global__ void __launch_bounds__(SOLVT, 1)
solve_kernel(float* __restrict__ out, int out_size) {
    extern __shared__ char smem[];
    uint4*    s_adj  = (uint4*)smem;                       // [NPTS]   128 KB: first 8 nbr ranks
    uint32_t* s_keep = (uint32_t*)(s_adj + NPTS);          // [256]      1 KB keep bitset
    uint8_t*  s_deg  = (uint8_t*)(s_keep + 256);           // [NPTS]     8 KB

    const int t = threadIdx.x;
    for (int r = t; r < NPTS; r += SOLVT) {
        s_adj[r] = *(const uint4*)&g_radj[r * MAXDEG];     // 16B = 8 x u16
        s_deg[r] = (uint8_t)min(g_acnt[r], MAXDEG);
    }
    __syncthreads();

    if (t < 32) {
        const int lane = t;
        for (int chunk = 0; chunk < 256; ++chunk) {
            const int base = chunk << 5;
            const int r    = base + lane;
            const int d    = s_deg[r];

            uint32_t kbase = 1u;       // AND over finalized (lower-chunk) nbrs
            uint32_t imask = 0u;       // intra-chunk nbr lanes (all rj < r)
            if (d) {
                const uint4 a = s_adj[r];
                const uint32_t w32[4] = {a.x, a.y, a.z, a.w};
                #pragma unroll
                for (int e = 0; e < 8; ++e) {
                    if (e < d) {
                        const uint32_t rj = (w32[e >> 1] >> ((e & 1) * 16)) & 0xFFFFu;
                        if ((int)rj >= base)
                            imask |= 1u << (rj - base);
                        else
                            kbase &= ~(s_keep[rj >> 5] >> (rj & 31)) & 1u;
                    }
                }
                for (int e = 8; e < d; ++e) {              // rare tail (deg > 8)
                    const uint32_t rj = g_radj[r * MAXDEG + e];
                    if ((int)rj >= base)
                        imask |= 1u << (rj - base);
                    else
                        kbase &= ~(s_keep[rj >> 5] >> (rj & 31)) & 1u;
                }
            }

            // ballot Jacobi on the 32-rank chunk (well-founded -> converges in depth)
            uint32_t w = __ballot_sync(0xFFFFFFFFu, kbase);
            for (;;) {
                const uint32_t k  = kbase & ((w & imask) == 0u ? 1u : 0u);
                const uint32_t nw = __ballot_sync(0xFFFFFFFFu, k);
                if (nw == w) break;
                w = nw;
            }
            if (lane == 0) s_keep[chunk] = w;
            __syncwarp();
        }
    }
    __syncthreads();

    // outputs: [keep_orig (0/1, original order), suppressed_scores (sorted order)]
    for (int r = t; r < NPTS; r += SOLVT) {
        const bool kept = (s_keep[r >> 5] >> (r & 31)) & 1u;
        if (out_size >= 2 * NPTS) {
            out[g_order[r]] = kept ? 1.0f : 0.0f;
            out[NPTS + r]   = kept ? g_ss[r] : 0.0f;
        } else {
            out[g_order[r]] = kept ? 1.0f : 0.0f;
        }
    }

    // re-zero atomic counters for the next replay (K2/K3 rely on zeros)
    if (t < NCELLS) g_ccnt[t] = 0;
    for (int r = t; r < NPTS; r += SOLVT) g_acnt[r] = 0;
}

extern "C" void kernel_launch(void* const* d_in, const int* in_sizes, int n_in,
                              void* d_out, int out_size) {
    const float* coords = (const float*)d_in[0];  // [N,2] f32
    const float* scores = (const float*)d_in[1];  // [N]   f32
    float* out = (float*)d_out;

    const int solve_smem = NPTS * (int)sizeof(uint4)      // s_adj  128 KB
                         + 256 * (int)sizeof(uint32_t)    // s_keep   1 KB
                         + NPTS;                          // s_deg    8 KB
    cudaFuncSetAttribute(solve_kernel,
                         cudaFuncAttributeMaxDynamicSharedMemorySize, solve_smem);

    dim3 rg(NPTS / 256, SPLIT);
    rank_partial_kernel<<<rg, 256>>>(scores);
    combine_fill_kernel<<<NPTS / 256, 256>>>(scores, coords);
    adj_kernel<<<(3 * NPTS) / 128, 128>>>(coords);
    solve_kernel<<<1, SOLVT, solve_smem>>>(out, out_size);
}